// round 1
// baseline (speedup 1.0000x reference)
#include <cuda_runtime.h>
#include <cuda_bf16.h>
#include <cstdint>

#define S_LEN 2048
#define D_DIM 1024
#define B_SZ  8

// 8 * 2048 * 2048 fp32 = 134 MB scratch for logits / probabilities.
static __device__ float g_scores[(size_t)B_SZ * S_LEN * S_LEN];

// ---------------------------------------------------------------------------
// helpers
// ---------------------------------------------------------------------------
__device__ __forceinline__ uint32_t f2tf32(float x) {
    uint32_t r;
    asm("cvt.rna.tf32.f32 %0, %1;" : "=r"(r) : "f"(x));
    return r;
}

__device__ __forceinline__ void mma_tf32(float* d, const uint32_t* a, const uint32_t* b) {
    asm volatile(
        "mma.sync.aligned.m16n8k8.row.col.f32.tf32.tf32.f32 "
        "{%0,%1,%2,%3}, {%4,%5,%6,%7}, {%8,%9}, {%0,%1,%2,%3};\n"
        : "+f"(d[0]), "+f"(d[1]), "+f"(d[2]), "+f"(d[3])
        : "r"(a[0]), "r"(a[1]), "r"(a[2]), "r"(a[3]), "r"(b[0]), "r"(b[1]));
}

__device__ __forceinline__ void cpa16(uint32_t saddr, const void* g) {
    asm volatile("cp.async.cg.shared.global [%0], [%1], 16;\n" :: "r"(saddr), "l"(g));
}
__device__ __forceinline__ void cpa_commit() { asm volatile("cp.async.commit_group;\n" ::); }
__device__ __forceinline__ void cpa_wait1()  { asm volatile("cp.async.wait_group 1;\n" ::); }
__device__ __forceinline__ void cpa_wait0()  { asm volatile("cp.async.wait_group 0;\n" ::); }

#define SA 20    // padded stride (floats) for 128x16 tiles -> conflict-free frag loads
#define SB 136   // padded stride (floats) for 16x128 V tile

// ---------------------------------------------------------------------------
// Kernel 1: scores = mask(Q @ K^T) / sqrt(D), lower-triangular tiles only.
// CTA tile 128x128, 8 warps (4m x 2n), warp tile 32x64, mma m16n8k8 tf32.
// ---------------------------------------------------------------------------
__global__ __launch_bounds__(256) void qk_kernel(const float* __restrict__ Q,
                                                 const float* __restrict__ K) {
    const int b  = blockIdx.z;
    const int q0 = blockIdx.y << 7;
    const int k0 = blockIdx.x << 7;
    if (k0 > q0 + 127) return;  // tile entirely above diagonal

    __shared__ float sQ[2][128 * SA];
    __shared__ float sK[2][128 * SA];

    const int tid = threadIdx.x;
    const float* Qb = Q + ((size_t)(b * S_LEN + q0)) * D_DIM;
    const float* Kb = K + ((size_t)(b * S_LEN + k0)) * D_DIM;

    const int lr = tid >> 2;          // 0..63
    const int lc = (tid & 3) << 2;    // 0,4,8,12
    const uint32_t sQb = (uint32_t)__cvta_generic_to_shared(sQ);
    const uint32_t sKb = (uint32_t)__cvta_generic_to_shared(sK);
    const uint32_t so0 = (uint32_t)((lr * SA + lc) * 4);
    const uint32_t so1 = (uint32_t)(((lr + 64) * SA + lc) * 4);
    const uint32_t stageBytes = 128 * SA * 4;

    const int warp = tid >> 5;
    const int wm = (warp & 3) * 32;
    const int wn = (warp >> 2) * 64;
    const int lane = tid & 31;
    const int grp = lane >> 2;
    const int tg  = lane & 3;

    float acc[2][8][4];
#pragma unroll
    for (int mi = 0; mi < 2; mi++)
#pragma unroll
        for (int ni = 0; ni < 8; ni++)
#pragma unroll
            for (int j = 0; j < 4; j++) acc[mi][ni][j] = 0.f;

    // prefetch chunk 0
    {
        const float* qp = Qb + (size_t)lr * D_DIM + lc;
        const float* kp = Kb + (size_t)lr * D_DIM + lc;
        cpa16(sQb + so0, qp);
        cpa16(sQb + so1, qp + (size_t)64 * D_DIM);
        cpa16(sKb + so0, kp);
        cpa16(sKb + so1, kp + (size_t)64 * D_DIM);
        cpa_commit();
    }

    const int NCH = D_DIM / 16;  // 64 chunks
    int st = 0;
    for (int ch = 0; ch < NCH; ch++) {
        if (ch + 1 < NCH) {
            const int d = (ch + 1) * 16;
            const float* qp = Qb + (size_t)lr * D_DIM + d + lc;
            const float* kp = Kb + (size_t)lr * D_DIM + d + lc;
            const uint32_t qs = sQb + (st ^ 1) * stageBytes;
            const uint32_t ks = sKb + (st ^ 1) * stageBytes;
            cpa16(qs + so0, qp);
            cpa16(qs + so1, qp + (size_t)64 * D_DIM);
            cpa16(ks + so0, kp);
            cpa16(ks + so1, kp + (size_t)64 * D_DIM);
            cpa_commit();
            cpa_wait1();
        } else {
            cpa_wait0();
        }
        __syncthreads();

        const float* q = sQ[st];
        const float* k = sK[st];
#pragma unroll
        for (int ks = 0; ks < 16; ks += 8) {
            uint32_t af[2][4], bf[8][2];
#pragma unroll
            for (int mi = 0; mi < 2; mi++) {
                const int rb = wm + mi * 16 + grp;
                af[mi][0] = f2tf32(q[rb * SA + ks + tg]);
                af[mi][1] = f2tf32(q[(rb + 8) * SA + ks + tg]);
                af[mi][2] = f2tf32(q[rb * SA + ks + tg + 4]);
                af[mi][3] = f2tf32(q[(rb + 8) * SA + ks + tg + 4]);
            }
#pragma unroll
            for (int ni = 0; ni < 8; ni++) {
                const int nb = wn + ni * 8 + grp;
                bf[ni][0] = f2tf32(k[nb * SA + ks + tg]);
                bf[ni][1] = f2tf32(k[nb * SA + ks + tg + 4]);
            }
#pragma unroll
            for (int mi = 0; mi < 2; mi++)
#pragma unroll
                for (int ni = 0; ni < 8; ni++) mma_tf32(acc[mi][ni], af[mi], bf[ni]);
        }
        __syncthreads();
        st ^= 1;
    }

    // epilogue: apply causal mask + 1/sqrt(1024) scale, write logits
    float* srow = g_scores + (size_t)b * S_LEN * S_LEN;
#pragma unroll
    for (int mi = 0; mi < 2; mi++) {
#pragma unroll
        for (int half = 0; half < 2; half++) {
            const int qg = q0 + wm + mi * 16 + grp + half * 8;
#pragma unroll
            for (int ni = 0; ni < 8; ni++) {
                const int kg = k0 + wn + ni * 8 + tg * 2;
                const float c0 = acc[mi][ni][half * 2 + 0];
                const float c1 = acc[mi][ni][half * 2 + 1];
                float2 v;
                v.x = (kg     > qg) ? -1.0e9f : c0 * 0.03125f;
                v.y = (kg + 1 > qg) ? -1.0e9f : c1 * 0.03125f;
                *reinterpret_cast<float2*>(&srow[(size_t)qg * S_LEN + kg]) = v;
            }
        }
    }
}

// ---------------------------------------------------------------------------
// Kernel 2: row-wise causal softmax, in place. One CTA (256 thr) per row;
// whole row lives in registers. Zero-fills (q, tile_boundary) so PV reads
// clean 128-wide tiles.
// ---------------------------------------------------------------------------
__global__ __launch_bounds__(256) void softmax_kernel() {
    const int q = blockIdx.x;
    const int b = blockIdx.y;
    float* row = g_scores + ((size_t)(b * S_LEN + q)) * S_LEN;
    const int tid = threadIdx.x;

    float v[8];
    float mx = -1e30f;
#pragma unroll
    for (int i = 0; i < 8; i++) {
        const int k = tid + (i << 8);
        v[i] = (k <= q) ? row[k] : -1e30f;
        mx = fmaxf(mx, v[i]);
    }

    __shared__ float red[8];
#pragma unroll
    for (int o = 16; o > 0; o >>= 1) mx = fmaxf(mx, __shfl_xor_sync(0xffffffffu, mx, o));
    if ((tid & 31) == 0) red[tid >> 5] = mx;
    __syncthreads();
    float m = red[0];
#pragma unroll
    for (int w = 1; w < 8; w++) m = fmaxf(m, red[w]);
    __syncthreads();

    float s = 0.f;
#pragma unroll
    for (int i = 0; i < 8; i++) {
        const int k = tid + (i << 8);
        const float p = (k <= q) ? __expf(v[i] - m) : 0.f;
        v[i] = p;
        s += p;
    }
#pragma unroll
    for (int o = 16; o > 0; o >>= 1) s += __shfl_xor_sync(0xffffffffu, s, o);
    if ((tid & 31) == 0) red[tid >> 5] = s;
    __syncthreads();
    float tot = 0.f;
#pragma unroll
    for (int w = 0; w < 8; w++) tot += red[w];

    const float inv = 1.f / tot;
    const int kb = ((q >> 7) + 1) << 7;  // zero-fill up to tile boundary
#pragma unroll
    for (int i = 0; i < 8; i++) {
        const int k = tid + (i << 8);
        if (k < kb) row[k] = v[i] * inv;
    }
}

// ---------------------------------------------------------------------------
// Kernel 3: O = P @ V with causal k-bound (k < q0 + 128).
// ---------------------------------------------------------------------------
__global__ __launch_bounds__(256) void pv_kernel(const float* __restrict__ V,
                                                 float* __restrict__ O) {
    const int b  = blockIdx.z;
    const int q0 = blockIdx.y << 7;
    const int d0 = blockIdx.x << 7;

    __shared__ float sA[2][128 * SA];
    __shared__ float sB[2][16 * SB];

    const int tid = threadIdx.x;
    const float* Pb = g_scores + ((size_t)(b * S_LEN + q0)) * S_LEN;
    const float* Vb = V + (size_t)b * S_LEN * D_DIM + d0;

    const uint32_t sAb = (uint32_t)__cvta_generic_to_shared(sA);
    const uint32_t sBb = (uint32_t)__cvta_generic_to_shared(sB);
    const int lr = tid >> 2;
    const int lc = (tid & 3) << 2;
    const uint32_t aoff0 = (uint32_t)((lr * SA + lc) * 4);
    const uint32_t aoff1 = (uint32_t)(((lr + 64) * SA + lc) * 4);
    const int br = tid >> 5;          // 0..7
    const int bc = (tid & 31) << 2;   // 0..124
    const uint32_t boff0 = (uint32_t)((br * SB + bc) * 4);
    const uint32_t boff1 = (uint32_t)(((br + 8) * SB + bc) * 4);
    const uint32_t stA = 128 * SA * 4, stB = 16 * SB * 4;

    const int warp = tid >> 5;
    const int wm = (warp & 3) * 32;
    const int wn = (warp >> 2) * 64;
    const int lane = tid & 31;
    const int grp = lane >> 2;
    const int tg  = lane & 3;

    float acc[2][8][4];
#pragma unroll
    for (int mi = 0; mi < 2; mi++)
#pragma unroll
        for (int ni = 0; ni < 8; ni++)
#pragma unroll
            for (int j = 0; j < 4; j++) acc[mi][ni][j] = 0.f;

    const int NCH = (q0 + 128) >> 4;  // causal bound on k-chunks

    // prefetch chunk 0
    {
        cpa16(sAb + aoff0, Pb + (size_t)lr * S_LEN + lc);
        cpa16(sAb + aoff1, Pb + (size_t)(lr + 64) * S_LEN + lc);
        cpa16(sBb + boff0, Vb + (size_t)br * D_DIM + bc);
        cpa16(sBb + boff1, Vb + (size_t)(br + 8) * D_DIM + bc);
        cpa_commit();
    }

    int st = 0;
    for (int ch = 0; ch < NCH; ch++) {
        if (ch + 1 < NCH) {
            const int kc = (ch + 1) * 16;
            const uint32_t as = sAb + (st ^ 1) * stA;
            const uint32_t bs = sBb + (st ^ 1) * stB;
            cpa16(as + aoff0, Pb + (size_t)lr * S_LEN + kc + lc);
            cpa16(as + aoff1, Pb + (size_t)(lr + 64) * S_LEN + kc + lc);
            cpa16(bs + boff0, Vb + (size_t)(kc + br) * D_DIM + bc);
            cpa16(bs + boff1, Vb + (size_t)(kc + br + 8) * D_DIM + bc);
            cpa_commit();
            cpa_wait1();
        } else {
            cpa_wait0();
        }
        __syncthreads();

        const float* a = sA[st];
        const float* vv = sB[st];
#pragma unroll
        for (int ks = 0; ks < 16; ks += 8) {
            uint32_t af[2][4], bf[8][2];
#pragma unroll
            for (int mi = 0; mi < 2; mi++) {
                const int rb = wm + mi * 16 + grp;
                af[mi][0] = f2tf32(a[rb * SA + ks + tg]);
                af[mi][1] = f2tf32(a[(rb + 8) * SA + ks + tg]);
                af[mi][2] = f2tf32(a[rb * SA + ks + tg + 4]);
                af[mi][3] = f2tf32(a[(rb + 8) * SA + ks + tg + 4]);
            }
#pragma unroll
            for (int ni = 0; ni < 8; ni++) {
                const int nb = wn + ni * 8 + grp;
                bf[ni][0] = f2tf32(vv[(ks + tg) * SB + nb]);
                bf[ni][1] = f2tf32(vv[(ks + tg + 4) * SB + nb]);
            }
#pragma unroll
            for (int mi = 0; mi < 2; mi++)
#pragma unroll
                for (int ni = 0; ni < 8; ni++) mma_tf32(acc[mi][ni], af[mi], bf[ni]);
        }
        __syncthreads();
        st ^= 1;
    }

    // epilogue: write O
#pragma unroll
    for (int mi = 0; mi < 2; mi++) {
#pragma unroll
        for (int half = 0; half < 2; half++) {
            const int qg = q0 + wm + mi * 16 + grp + half * 8;
            float* orow = O + ((size_t)(b * S_LEN + qg)) * D_DIM + d0;
#pragma unroll
            for (int ni = 0; ni < 8; ni++) {
                const int cg = wn + ni * 8 + tg * 2;
                float2 v;
                v.x = acc[mi][ni][half * 2 + 0];
                v.y = acc[mi][ni][half * 2 + 1];
                *reinterpret_cast<float2*>(&orow[cg]) = v;
            }
        }
    }
}

// ---------------------------------------------------------------------------
extern "C" void kernel_launch(void* const* d_in, const int* in_sizes, int n_in,
                              void* d_out, int out_size) {
    const float* Q = (const float*)d_in[0];
    const float* K = (const float*)d_in[1];
    const float* V = (const float*)d_in[2];
    float* O = (float*)d_out;

    qk_kernel<<<dim3(16, 16, 8), 256>>>(Q, K);
    softmax_kernel<<<dim3(2048, 8), 256>>>();
    pv_kernel<<<dim3(8, 16, 8), 256>>>(V, O);
}

// round 3
// speedup vs baseline: 1.0749x; 1.0749x over previous
#include <cuda_runtime.h>
#include <cstdint>

#define S_LEN 2048
#define D_DIM 1024
#define B_SZ  8

// Scratch (static __device__ per allocation rules)
static __device__ float g_scores[(size_t)B_SZ * S_LEN * S_LEN];   // logits -> P (permuted)
static __device__ float g_qp[(size_t)B_SZ * S_LEN * D_DIM];       // Q rounded+permuted
static __device__ float g_kp[(size_t)B_SZ * S_LEN * D_DIM];       // K rounded+permuted
static __device__ float g_vt[(size_t)B_SZ * D_DIM * S_LEN];       // V^T rounded+permuted

// ---------------------------------------------------------------------------
// helpers
// ---------------------------------------------------------------------------
__device__ __forceinline__ uint32_t f2tf32(float x) {
    uint32_t r; asm("cvt.rna.tf32.f32 %0, %1;" : "=r"(r) : "f"(x)); return r;
}
__device__ __forceinline__ float rtf(float x) { return __uint_as_float(f2tf32(x)); }

__device__ __forceinline__ void mma_tf32(float* d, const uint32_t* a, const uint32_t* b) {
    asm volatile(
        "mma.sync.aligned.m16n8k8.row.col.f32.tf32.tf32.f32 "
        "{%0,%1,%2,%3}, {%4,%5,%6,%7}, {%8,%9}, {%0,%1,%2,%3};\n"
        : "+f"(d[0]), "+f"(d[1]), "+f"(d[2]), "+f"(d[3])
        : "r"(a[0]), "r"(a[1]), "r"(a[2]), "r"(a[3]), "r"(b[0]), "r"(b[1]));
}

__device__ __forceinline__ void cpa16(uint32_t s, const void* g) {
    asm volatile("cp.async.cg.shared.global [%0], [%1], 16;" :: "r"(s), "l"(g));
}
__device__ __forceinline__ void cpa_commit() { asm volatile("cp.async.commit_group;" ::); }
__device__ __forceinline__ void cpa_wait1()  { asm volatile("cp.async.wait_group 1;" ::); }
__device__ __forceinline__ void cpa_wait0()  { asm volatile("cp.async.wait_group 0;" ::); }

// within-16 permutation position of original index t (pairs (t, t+4) adjacent)
__device__ __forceinline__ int pos16(int t) {
    return (t & 8) | ((t & 3) << 1) | ((t >> 2) & 1);
}

// Load fragment pair {X[row][ks+tg], X[row][ks+tg+4]} from permuted+swizzled tile.
// Tile: 128 rows x 16 floats (64B), 16B block swizzled by (blk ^ (row & 3)).
// granule g = ks/2 + tg  (pair index 0..7)
__device__ __forceinline__ uint2 ld2(const float* base, int row, int g) {
    const int off = row * 16 + (((g >> 1) ^ (row & 3)) << 2) + ((g & 1) << 1);
    return *reinterpret_cast<const uint2*>(base + off);
}

// cp.async one 128x16 tile (2 blocks of 16B per thread, 256 threads)
__device__ __forceinline__ void load_tile(uint32_t sbase, const float* src,
                                          int ld, int ch, int tid) {
#pragma unroll
    for (int t = 0; t < 2; t++) {
        const int idx = tid + (t << 8);          // 0..511
        const int row = idx >> 2;                // 0..127
        const int blk = idx & 3;                 // 0..3
        const uint32_t dst = sbase + (uint32_t)(row * 64 + ((blk ^ (row & 3)) << 4));
        cpa16(dst, src + (size_t)row * ld + ch * 16 + blk * 4);
    }
}

// ---------------------------------------------------------------------------
// Shared GEMM core: C[128x128] += A[128xK] * B[128xK]^T over NCH 16-k chunks.
// 8 warps, warp tile 32x64 (4m x 2n warp grid). acc[2][8][4] per thread.
// ---------------------------------------------------------------------------
struct Frag { float acc[2][8][4]; };

__device__ __forceinline__ void gemm_core(Frag& F, float (*sA)[128 * 16],
                                          float (*sB)[128 * 16],
                                          const float* Asrc, int lda,
                                          const float* Bsrc, int ldb, int NCH) {
    const int tid = threadIdx.x;
    const int warp = tid >> 5;
    const int wm = (warp & 3) * 32;
    const int wn = (warp >> 2) * 64;
    const int lane = tid & 31;
    const int grp = lane >> 3;      // NOTE: mma row group = lane>>2 -- see below
    (void)grp;
    const int qr = lane >> 2;       // 0..7 fragment row group
    const int tg = lane & 3;        // 0..3 fragment k group

#pragma unroll
    for (int mi = 0; mi < 2; mi++)
#pragma unroll
        for (int ni = 0; ni < 8; ni++)
#pragma unroll
            for (int j = 0; j < 4; j++) F.acc[mi][ni][j] = 0.f;

    const uint32_t sAb = (uint32_t)__cvta_generic_to_shared(sA);
    const uint32_t sBb = (uint32_t)__cvta_generic_to_shared(sB);
    const uint32_t stageBytes = 128 * 16 * 4;

    load_tile(sAb, Asrc, lda, 0, tid);
    load_tile(sBb, Bsrc, ldb, 0, tid);
    cpa_commit();

    int st = 0;
    for (int ch = 0; ch < NCH; ch++) {
        if (ch + 1 < NCH) {
            const uint32_t as = sAb + (st ^ 1) * stageBytes;
            const uint32_t bs = sBb + (st ^ 1) * stageBytes;
            load_tile(as, Asrc, lda, ch + 1, tid);
            load_tile(bs, Bsrc, ldb, ch + 1, tid);
            cpa_commit();
            cpa_wait1();
        } else {
            cpa_wait0();
        }
        __syncthreads();

        const float* A = sA[st];
        const float* B = sB[st];
#pragma unroll
        for (int ks2 = 0; ks2 < 2; ks2++) {
            const int g = ks2 * 4 + tg;
            uint32_t af[2][4];
#pragma unroll
            for (int mi = 0; mi < 2; mi++) {
                const int rb = wm + mi * 16 + qr;
                const uint2 L0 = ld2(A, rb, g);
                const uint2 L1 = ld2(A, rb + 8, g);
                af[mi][0] = L0.x; af[mi][1] = L1.x;
                af[mi][2] = L0.y; af[mi][3] = L1.y;
            }
            uint32_t bf[8][2];
#pragma unroll
            for (int ni = 0; ni < 8; ni++) {
                const int nb = wn + ni * 8 + qr;
                const uint2 Lb = ld2(B, nb, g);
                bf[ni][0] = Lb.x; bf[ni][1] = Lb.y;
            }
#pragma unroll
            for (int mi = 0; mi < 2; mi++)
#pragma unroll
                for (int ni = 0; ni < 8; ni++) mma_tf32(F.acc[mi][ni], af[mi], bf[ni]);
        }
        __syncthreads();
        st ^= 1;
    }
}

// ---------------------------------------------------------------------------
// Kernel 1: logits = mask(Q @ K^T) * 0.03125  (lower-triangular tiles only)
// ---------------------------------------------------------------------------
__global__ __launch_bounds__(256) void qk_kernel() {
    const int b  = blockIdx.z;
    const int q0 = blockIdx.y << 7;
    const int k0 = blockIdx.x << 7;
    if (k0 > q0) return;

    __shared__ float sA[2][128 * 16];
    __shared__ float sB[2][128 * 16];

    Frag F;
    gemm_core(F, sA, sB,
              g_qp + ((size_t)(b * S_LEN + q0)) * D_DIM, D_DIM,
              g_kp + ((size_t)(b * S_LEN + k0)) * D_DIM, D_DIM, D_DIM / 16);

    const int tid = threadIdx.x;
    const int warp = tid >> 5;
    const int wm = (warp & 3) * 32;
    const int wn = (warp >> 2) * 64;
    const int lane = tid & 31;
    const int qr = lane >> 2;
    const int tg = lane & 3;

    float* srow = g_scores + (size_t)b * S_LEN * S_LEN;
#pragma unroll
    for (int mi = 0; mi < 2; mi++) {
#pragma unroll
        for (int half = 0; half < 2; half++) {
            const int qg = q0 + wm + mi * 16 + qr + half * 8;
#pragma unroll
            for (int ni = 0; ni < 8; ni++) {
                const int kg = k0 + wn + ni * 8 + tg * 2;
                float2 v;
                v.x = (kg     > qg) ? -1e9f : F.acc[mi][ni][half * 2 + 0] * 0.03125f;
                v.y = (kg + 1 > qg) ? -1e9f : F.acc[mi][ni][half * 2 + 1] * 0.03125f;
                *reinterpret_cast<float2*>(&srow[(size_t)qg * S_LEN + kg]) = v;
            }
        }
    }
}

// ---------------------------------------------------------------------------
// Kernel 2: row softmax (causal). Reads plain order, writes P permuted
// (within-16 k-groups) + tf32-rounded, zero-filled to 128 boundary.
// ---------------------------------------------------------------------------
__global__ __launch_bounds__(256) void softmax_kernel() {
    const int q = blockIdx.x;
    const int b = blockIdx.y;
    float* row = g_scores + ((size_t)(b * S_LEN + q)) * S_LEN;
    const int tid = threadIdx.x;

    float v[8];
    float mx = -1e30f;
#pragma unroll
    for (int i = 0; i < 8; i++) {
        const int k = tid + (i << 8);
        v[i] = (k <= q) ? row[k] : -1e30f;
        mx = fmaxf(mx, v[i]);
    }
    __shared__ float red[8];
#pragma unroll
    for (int o = 16; o > 0; o >>= 1) mx = fmaxf(mx, __shfl_xor_sync(0xffffffffu, mx, o));
    if ((tid & 31) == 0) red[tid >> 5] = mx;
    __syncthreads();
    float m = red[0];
#pragma unroll
    for (int w = 1; w < 8; w++) m = fmaxf(m, red[w]);
    __syncthreads();

    float s = 0.f;
#pragma unroll
    for (int i = 0; i < 8; i++) {
        const int k = tid + (i << 8);
        const float p = (k <= q) ? __expf(v[i] - m) : 0.f;
        v[i] = p;
        s += p;
    }
#pragma unroll
    for (int o = 16; o > 0; o >>= 1) s += __shfl_xor_sync(0xffffffffu, s, o);
    if ((tid & 31) == 0) red[tid >> 5] = s;
    __syncthreads();
    float tot = 0.f;
#pragma unroll
    for (int w = 0; w < 8; w++) tot += red[w];

    const float inv = 1.f / tot;
    const int kb = ((q >> 7) + 1) << 7;
#pragma unroll
    for (int i = 0; i < 8; i++) {
        const int k = tid + (i << 8);
        if (k < kb) {
            const int kp = (k & ~15) | pos16(k & 15);
            row[kp] = rtf(v[i] * inv);
        }
    }
}

// ---------------------------------------------------------------------------
// Kernel 3: O = P @ V  via B = V^T (rounded+permuted), causal chunk bound.
// ---------------------------------------------------------------------------
__global__ __launch_bounds__(256) void pv_kernel(float* __restrict__ O) {
    const int b  = blockIdx.z;
    const int q0 = blockIdx.y << 7;
    const int d0 = blockIdx.x << 7;

    __shared__ float sA[2][128 * 16];
    __shared__ float sB[2][128 * 16];

    Frag F;
    const int NCH = (q0 + 128) >> 4;
    gemm_core(F, sA, sB,
              g_scores + ((size_t)(b * S_LEN + q0)) * S_LEN, S_LEN,
              g_vt + ((size_t)(b * D_DIM + d0)) * S_LEN, S_LEN, NCH);

    const int tid = threadIdx.x;
    const int warp = tid >> 5;
    const int wm = (warp & 3) * 32;
    const int wn = (warp >> 2) * 64;
    const int lane = tid & 31;
    const int qr = lane >> 2;
    const int tg = lane & 3;

#pragma unroll
    for (int mi = 0; mi < 2; mi++) {
#pragma unroll
        for (int half = 0; half < 2; half++) {
            const int qg = q0 + wm + mi * 16 + qr + half * 8;
            float* orow = O + ((size_t)(b * S_LEN + qg)) * D_DIM + d0;
#pragma unroll
            for (int ni = 0; ni < 8; ni++) {
                const int cg = wn + ni * 8 + tg * 2;
                float2 v;
                v.x = F.acc[mi][ni][half * 2 + 0];
                v.y = F.acc[mi][ni][half * 2 + 1];
                *reinterpret_cast<float2*>(&orow[cg]) = v;
            }
        }
    }
}

// ---------------------------------------------------------------------------
// Pre-pass: round Q,K to tf32 and permute within 16-float groups.
// position p holds original t(p) = (p&8) | ((p>>1)&3) | ((p&1)<<2)
// ---------------------------------------------------------------------------
__global__ __launch_bounds__(256) void round_perm_qk(const float* __restrict__ Q,
                                                     const float* __restrict__ K) {
    const size_t i = (size_t)blockIdx.x * blockDim.x + threadIdx.x;
    const float* src = (blockIdx.y == 0 ? Q : K) + i * 16;
    float* dst = (blockIdx.y == 0 ? g_qp : g_kp) + i * 16;
    float f[16];
#pragma unroll
    for (int j = 0; j < 16; j += 4)
        *reinterpret_cast<float4*>(f + j) = *reinterpret_cast<const float4*>(src + j);
    float4 o;
    o.x = rtf(f[0]);  o.y = rtf(f[4]);  o.z = rtf(f[1]);  o.w = rtf(f[5]);
    *reinterpret_cast<float4*>(dst + 0) = o;
    o.x = rtf(f[2]);  o.y = rtf(f[6]);  o.z = rtf(f[3]);  o.w = rtf(f[7]);
    *reinterpret_cast<float4*>(dst + 4) = o;
    o.x = rtf(f[8]);  o.y = rtf(f[12]); o.z = rtf(f[9]);  o.w = rtf(f[13]);
    *reinterpret_cast<float4*>(dst + 8) = o;
    o.x = rtf(f[10]); o.y = rtf(f[14]); o.z = rtf(f[11]); o.w = rtf(f[15]);
    *reinterpret_cast<float4*>(dst + 12) = o;
}

// ---------------------------------------------------------------------------
// Pre-pass: V^T with tf32 rounding + within-16 k permutation.
// g_vt[b][d][perm(k)] = round(V[b][k][d])
// ---------------------------------------------------------------------------
__global__ __launch_bounds__(256) void transpose_v_kernel(const float* __restrict__ V) {
    __shared__ float tile[32][33];
    const int b  = blockIdx.z;
    const int k0 = blockIdx.x << 5;
    const int d0 = blockIdx.y << 5;
    const int tx = threadIdx.x & 31, ty = threadIdx.x >> 5;
    const float* Vb = V + (size_t)b * S_LEN * D_DIM;
#pragma unroll
    for (int i = 0; i < 4; i++)
        tile[ty + 8 * i][tx] = Vb[(size_t)(k0 + ty + 8 * i) * D_DIM + d0 + tx];
    __syncthreads();
    float* Tb = g_vt + (size_t)b * D_DIM * S_LEN;
    const int kcol = k0 + (tx & 16) + pos16(tx & 15);
#pragma unroll
    for (int i = 0; i < 4; i++)
        Tb[(size_t)(d0 + ty + 8 * i) * S_LEN + kcol] = rtf(tile[tx][ty + 8 * i]);
}

// ---------------------------------------------------------------------------
extern "C" void kernel_launch(void* const* d_in, const int* in_sizes, int n_in,
                              void* d_out, int out_size) {
    const float* Q = (const float*)d_in[0];
    const float* K = (const float*)d_in[1];
    const float* V = (const float*)d_in[2];
    float* O = (float*)d_out;

    // 8*2048*1024 elems / 16 per thread / 256 threads = 4096 blocks
    round_perm_qk<<<dim3(4096, 2), 256>>>(Q, K);
    transpose_v_kernel<<<dim3(64, 32, 8), 256>>>(V);
    qk_kernel<<<dim3(16, 16, 8), 256>>>();
    softmax_kernel<<<dim3(2048, 8), 256>>>();
    pv_kernel<<<dim3(8, 16, 8), 256>>>(O);
}

// round 4
// speedup vs baseline: 2.3864x; 2.2201x over previous
#include <cuda_runtime.h>
#include <cuda_fp16.h>
#include <cstdint>

#define S_LEN 2048
#define D_DIM 1024
#define B_SZ  8

// Scratch (static __device__ per allocation rules)
static __device__ float  g_scores[(size_t)B_SZ * S_LEN * S_LEN];  // fp32 logits
static __device__ __half g_ph[(size_t)B_SZ * S_LEN * S_LEN];      // P (half)
static __device__ __half g_qh[(size_t)B_SZ * S_LEN * D_DIM];      // Q half
static __device__ __half g_kh[(size_t)B_SZ * S_LEN * D_DIM];      // K half
static __device__ __half g_vth[(size_t)B_SZ * D_DIM * S_LEN];     // V^T half

// ---------------------------------------------------------------------------
// helpers
// ---------------------------------------------------------------------------
__device__ __forceinline__ void mma_f16(float* d, const uint32_t* a, uint32_t b0, uint32_t b1) {
    asm volatile(
        "mma.sync.aligned.m16n8k16.row.col.f32.f16.f16.f32 "
        "{%0,%1,%2,%3}, {%4,%5,%6,%7}, {%8,%9}, {%0,%1,%2,%3};\n"
        : "+f"(d[0]), "+f"(d[1]), "+f"(d[2]), "+f"(d[3])
        : "r"(a[0]), "r"(a[1]), "r"(a[2]), "r"(a[3]), "r"(b0), "r"(b1));
}
__device__ __forceinline__ void ldsm4(uint32_t* r, uint32_t addr) {
    asm volatile("ldmatrix.sync.aligned.m8n8.x4.shared.b16 {%0,%1,%2,%3}, [%4];"
                 : "=r"(r[0]), "=r"(r[1]), "=r"(r[2]), "=r"(r[3]) : "r"(addr));
}
__device__ __forceinline__ void cpa16(uint32_t s, const void* g) {
    asm volatile("cp.async.cg.shared.global [%0], [%1], 16;" :: "r"(s), "l"(g));
}
__device__ __forceinline__ void cpa_commit() { asm volatile("cp.async.commit_group;" ::); }
__device__ __forceinline__ void cpa_wait1()  { asm volatile("cp.async.wait_group 1;" ::); }
__device__ __forceinline__ void cpa_wait0()  { asm volatile("cp.async.wait_group 0;" ::); }

// Tile: 128 rows x 64 halves (128B/row, 8 x 16B chunks). Chunk c of row r is
// stored at r*128 + ((c ^ (r&7))<<4)  -> ldmatrix (8 consecutive rows, same c)
// hits 8 distinct 16B slots per 128B phase: conflict-free.
#define TILE_BYTES 16384
#define SMEM_BYTES 65536   // A[2] + B[2]

// cp.async one 128x64-half tile (4 x 16B per thread, 256 threads)
__device__ __forceinline__ void load_tile(uint32_t base, const __half* src,
                                          int ld, int ch, int tid) {
#pragma unroll
    for (int t = 0; t < 4; t++) {
        const int idx = tid + (t << 8);          // 0..1023
        const int r = idx >> 3;                  // 0..127
        const int c = idx & 7;                   // 0..7
        const uint32_t dst = base + (uint32_t)(r * 128 + ((c ^ (r & 7)) << 4));
        cpa16(dst, src + (size_t)r * ld + ch * 64 + c * 8);
    }
}

// ---------------------------------------------------------------------------
// GEMM core: C[128x128] += A[128xK] * B[128xK]^T, half inputs, fp32 accum.
// 8 warps (4m x 2n), warp tile 32x64, mma m16n8k16. K-chunk = 64.
// ---------------------------------------------------------------------------
struct Frag { float acc[2][8][4]; };

__device__ __forceinline__ void gemm_core(Frag& F, char* dsm,
                                          const __half* Asrc, int lda,
                                          const __half* Bsrc, int ldb, int NCH) {
    const int tid = threadIdx.x;
    const int warp = tid >> 5;
    const int wm = (warp & 3) * 32;
    const int wn = (warp >> 2) * 64;
    const int lane = tid & 31;

#pragma unroll
    for (int mi = 0; mi < 2; mi++)
#pragma unroll
        for (int ni = 0; ni < 8; ni++)
#pragma unroll
            for (int j = 0; j < 4; j++) F.acc[mi][ni][j] = 0.f;

    uint32_t sb;
    asm("{ .reg .u64 t; cvta.to.shared.u64 t, %1; cvt.u32.u64 %0, t; }" : "=r"(sb) : "l"(dsm));
    const uint32_t sA0 = sb;                    // A stages at 0, 16K
    const uint32_t sB0 = sb + 2 * TILE_BYTES;   // B stages at 32K, 48K

    // ldmatrix address precompute
    const int rA = wm + ((lane >> 3) & 1) * 8 + (lane & 7);   // mi adds 16
    const int cShA = lane >> 4;                                // chunk parity
    const uint32_t baseA0 = (uint32_t)(rA * 128);
    const uint32_t baseA1 = (uint32_t)((rA + 16) * 128);
    const int swA = rA & 7;
    const int rB = wn + ((lane >> 4) & 1) * 8 + (lane & 7);   // nb2 adds 16
    const int cShB = (lane >> 3) & 1;
    const int swB = rB & 7;
    uint32_t baseB[4];
#pragma unroll
    for (int nb = 0; nb < 4; nb++) baseB[nb] = (uint32_t)((rB + 16 * nb) * 128);

    load_tile(sA0, Asrc, lda, 0, tid);
    load_tile(sB0, Bsrc, ldb, 0, tid);
    cpa_commit();

    int st = 0;
    for (int ch = 0; ch < NCH; ch++) {
        if (ch + 1 < NCH) {
            load_tile(sA0 + (st ^ 1) * TILE_BYTES, Asrc, lda, ch + 1, tid);
            load_tile(sB0 + (st ^ 1) * TILE_BYTES, Bsrc, ldb, ch + 1, tid);
            cpa_commit();
            cpa_wait1();
        } else {
            cpa_wait0();
        }
        __syncthreads();

        const uint32_t aStage = sA0 + st * TILE_BYTES;
        const uint32_t bStage = sB0 + st * TILE_BYTES;
#pragma unroll
        for (int kk = 0; kk < 4; kk++) {   // four k16 steps in a k64 chunk
            uint32_t af[2][4], bf[4][4];
            const uint32_t offA = (uint32_t)((((2 * kk + cShA) ^ swA)) << 4);
            ldsm4(af[0], aStage + baseA0 + offA);
            ldsm4(af[1], aStage + baseA1 + offA);
            const uint32_t offB = (uint32_t)((((2 * kk + cShB) ^ swB)) << 4);
#pragma unroll
            for (int nb = 0; nb < 4; nb++) ldsm4(bf[nb], bStage + baseB[nb] + offB);
#pragma unroll
            for (int mi = 0; mi < 2; mi++)
#pragma unroll
                for (int ni = 0; ni < 8; ni++)
                    mma_f16(F.acc[mi][ni], af[mi],
                            bf[ni >> 1][(ni & 1) * 2], bf[ni >> 1][(ni & 1) * 2 + 1]);
        }
        __syncthreads();
        st ^= 1;
    }
}

// ---------------------------------------------------------------------------
// Kernel 1: logits = mask(Q @ K^T) * 0.03125  (lower-triangular tiles only)
// ---------------------------------------------------------------------------
__global__ __launch_bounds__(256, 2) void qk_kernel() {
    const int b  = blockIdx.z;
    const int q0 = blockIdx.y << 7;
    const int k0 = blockIdx.x << 7;
    if (k0 > q0) return;

    extern __shared__ __align__(16) char dsm[];
    Frag F;
    gemm_core(F, dsm,
              g_qh + ((size_t)(b * S_LEN + q0)) * D_DIM, D_DIM,
              g_kh + ((size_t)(b * S_LEN + k0)) * D_DIM, D_DIM, D_DIM / 64);

    const int tid = threadIdx.x;
    const int warp = tid >> 5;
    const int wm = (warp & 3) * 32;
    const int wn = (warp >> 2) * 64;
    const int lane = tid & 31;
    const int qr = lane >> 2;
    const int tg = lane & 3;

    float* srow = g_scores + (size_t)b * S_LEN * S_LEN;
#pragma unroll
    for (int mi = 0; mi < 2; mi++) {
#pragma unroll
        for (int half = 0; half < 2; half++) {
            const int qg = q0 + wm + mi * 16 + qr + half * 8;
#pragma unroll
            for (int ni = 0; ni < 8; ni++) {
                const int kg = k0 + wn + ni * 8 + tg * 2;
                float2 v;
                v.x = (kg     > qg) ? -1e9f : F.acc[mi][ni][half * 2 + 0] * 0.03125f;
                v.y = (kg + 1 > qg) ? -1e9f : F.acc[mi][ni][half * 2 + 1] * 0.03125f;
                *reinterpret_cast<float2*>(&srow[(size_t)qg * S_LEN + kg]) = v;
            }
        }
    }
}

// ---------------------------------------------------------------------------
// Kernel 2: row softmax (causal), writes half P zero-filled to 128 boundary.
// ---------------------------------------------------------------------------
__global__ __launch_bounds__(256) void softmax_kernel() {
    const int q = blockIdx.x;
    const int b = blockIdx.y;
    const float* row = g_scores + ((size_t)(b * S_LEN + q)) * S_LEN;
    __half* prow = g_ph + ((size_t)(b * S_LEN + q)) * S_LEN;
    const int tid = threadIdx.x;

    float v[8];
    float mx = -1e30f;
#pragma unroll
    for (int i = 0; i < 8; i++) {
        const int k = tid + (i << 8);
        v[i] = (k <= q) ? row[k] : -1e30f;
        mx = fmaxf(mx, v[i]);
    }
    __shared__ float red[8];
#pragma unroll
    for (int o = 16; o > 0; o >>= 1) mx = fmaxf(mx, __shfl_xor_sync(0xffffffffu, mx, o));
    if ((tid & 31) == 0) red[tid >> 5] = mx;
    __syncthreads();
    float m = red[0];
#pragma unroll
    for (int w = 1; w < 8; w++) m = fmaxf(m, red[w]);
    __syncthreads();

    float s = 0.f;
#pragma unroll
    for (int i = 0; i < 8; i++) {
        const int k = tid + (i << 8);
        const float p = (k <= q) ? __expf(v[i] - m) : 0.f;
        v[i] = p;
        s += p;
    }
#pragma unroll
    for (int o = 16; o > 0; o >>= 1) s += __shfl_xor_sync(0xffffffffu, s, o);
    if ((tid & 31) == 0) red[tid >> 5] = s;
    __syncthreads();
    float tot = 0.f;
#pragma unroll
    for (int w = 0; w < 8; w++) tot += red[w];

    const float inv = 1.f / tot;
    const int kb = ((q >> 7) + 1) << 7;
#pragma unroll
    for (int i = 0; i < 8; i++) {
        const int k = tid + (i << 8);
        if (k < kb) prow[k] = __float2half(v[i] * inv);
    }
}

// ---------------------------------------------------------------------------
// Kernel 3: O = P @ V  (B = V^T half, causal chunk bound)
// ---------------------------------------------------------------------------
__global__ __launch_bounds__(256, 2) void pv_kernel(float* __restrict__ O) {
    const int b  = blockIdx.z;
    const int q0 = blockIdx.y << 7;
    const int d0 = blockIdx.x << 7;

    extern __shared__ __align__(16) char dsm[];
    Frag F;
    const int NCH = (q0 + 128) >> 6;
    gemm_core(F, dsm,
              g_ph + ((size_t)(b * S_LEN + q0)) * S_LEN, S_LEN,
              g_vth + ((size_t)(b * D_DIM + d0)) * S_LEN, S_LEN, NCH);

    const int tid = threadIdx.x;
    const int warp = tid >> 5;
    const int wm = (warp & 3) * 32;
    const int wn = (warp >> 2) * 64;
    const int lane = tid & 31;
    const int qr = lane >> 2;
    const int tg = lane & 3;

#pragma unroll
    for (int mi = 0; mi < 2; mi++) {
#pragma unroll
        for (int half = 0; half < 2; half++) {
            const int qg = q0 + wm + mi * 16 + qr + half * 8;
            float* orow = O + ((size_t)(b * S_LEN + qg)) * D_DIM + d0;
#pragma unroll
            for (int ni = 0; ni < 8; ni++) {
                const int cg = wn + ni * 8 + tg * 2;
                float2 v;
                v.x = F.acc[mi][ni][half * 2 + 0];
                v.y = F.acc[mi][ni][half * 2 + 1];
                *reinterpret_cast<float2*>(&orow[cg]) = v;
            }
        }
    }
}

// ---------------------------------------------------------------------------
// Pre-pass: Q,K -> half (plain row-major)
// ---------------------------------------------------------------------------
__global__ __launch_bounds__(256) void conv_qk(const float4* __restrict__ Q,
                                               const float4* __restrict__ K) {
    const size_t i = (size_t)blockIdx.x * blockDim.x + threadIdx.x;  // 8 floats each
    const float4* src = blockIdx.y == 0 ? Q : K;
    __half* dst = blockIdx.y == 0 ? g_qh : g_kh;
    const float4 a = src[2 * i];
    const float4 b = src[2 * i + 1];
    __half2 h[4];
    h[0] = __floats2half2_rn(a.x, a.y);
    h[1] = __floats2half2_rn(a.z, a.w);
    h[2] = __floats2half2_rn(b.x, b.y);
    h[3] = __floats2half2_rn(b.z, b.w);
    *reinterpret_cast<uint4*>(dst + i * 8) = *reinterpret_cast<uint4*>(h);
}

// ---------------------------------------------------------------------------
// Pre-pass: V^T -> half.  g_vth[b][d][k] = (half)V[b][k][d]
// ---------------------------------------------------------------------------
__global__ __launch_bounds__(256) void transpose_v_kernel(const float* __restrict__ V) {
    __shared__ float tile[32][33];
    const int b  = blockIdx.z;
    const int k0 = blockIdx.x << 5;
    const int d0 = blockIdx.y << 5;
    const int tx = threadIdx.x & 31, ty = threadIdx.x >> 5;
    const float* Vb = V + (size_t)b * S_LEN * D_DIM;
#pragma unroll
    for (int i = 0; i < 4; i++)
        tile[ty + 8 * i][tx] = Vb[(size_t)(k0 + ty + 8 * i) * D_DIM + d0 + tx];
    __syncthreads();
    __half* Tb = g_vth + (size_t)b * D_DIM * S_LEN;
#pragma unroll
    for (int i = 0; i < 4; i++)
        Tb[(size_t)(d0 + ty + 8 * i) * S_LEN + k0 + tx] = __float2half(tile[tx][ty + 8 * i]);
}

// ---------------------------------------------------------------------------
extern "C" void kernel_launch(void* const* d_in, const int* in_sizes, int n_in,
                              void* d_out, int out_size) {
    const float* Q = (const float*)d_in[0];
    const float* K = (const float*)d_in[1];
    const float* V = (const float*)d_in[2];
    float* O = (float*)d_out;

    static bool attr_done = false;
    if (!attr_done) {
        cudaFuncSetAttribute(qk_kernel, cudaFuncAttributeMaxDynamicSharedMemorySize, SMEM_BYTES);
        cudaFuncSetAttribute(pv_kernel, cudaFuncAttributeMaxDynamicSharedMemorySize, SMEM_BYTES);
        attr_done = true;
    }

    conv_qk<<<dim3(8192, 2), 256>>>((const float4*)Q, (const float4*)K);
    transpose_v_kernel<<<dim3(64, 32, 8), 256>>>(V);
    qk_kernel<<<dim3(16, 16, 8), 256, SMEM_BYTES>>>();
    softmax_kernel<<<dim3(2048, 8), 256>>>();
    pv_kernel<<<dim3(8, 16, 8), 256, SMEM_BYTES>>>(O);
}

// round 5
// speedup vs baseline: 2.4679x; 1.0341x over previous
#include <cuda_runtime.h>
#include <cuda_fp16.h>
#include <cstdint>

#define S_LEN 2048
#define D_DIM 1024
#define B_SZ  8

// Scratch (static __device__ per allocation rules)
static __device__ float  g_scores[(size_t)B_SZ * S_LEN * S_LEN];  // fp32 logits
static __device__ __half g_ph[(size_t)B_SZ * S_LEN * S_LEN];      // P (half)
static __device__ __half g_qh[(size_t)B_SZ * S_LEN * D_DIM];      // Q half
static __device__ __half g_kh[(size_t)B_SZ * S_LEN * D_DIM];      // K half
static __device__ __half g_vth[(size_t)B_SZ * D_DIM * S_LEN];     // V^T half

// ---------------------------------------------------------------------------
// helpers
// ---------------------------------------------------------------------------
__device__ __forceinline__ void mma_f16(float* d, const uint32_t* a, uint32_t b0, uint32_t b1) {
    asm volatile(
        "mma.sync.aligned.m16n8k16.row.col.f32.f16.f16.f32 "
        "{%0,%1,%2,%3}, {%4,%5,%6,%7}, {%8,%9}, {%0,%1,%2,%3};\n"
        : "+f"(d[0]), "+f"(d[1]), "+f"(d[2]), "+f"(d[3])
        : "r"(a[0]), "r"(a[1]), "r"(a[2]), "r"(a[3]), "r"(b0), "r"(b1));
}
__device__ __forceinline__ void ldsm4(uint32_t* r, uint32_t addr) {
    asm volatile("ldmatrix.sync.aligned.m8n8.x4.shared.b16 {%0,%1,%2,%3}, [%4];"
                 : "=r"(r[0]), "=r"(r[1]), "=r"(r[2]), "=r"(r[3]) : "r"(addr));
}
__device__ __forceinline__ void cpa16(uint32_t s, const void* g) {
    asm volatile("cp.async.cg.shared.global [%0], [%1], 16;" :: "r"(s), "l"(g));
}
__device__ __forceinline__ void cpa_commit() { asm volatile("cp.async.commit_group;" ::); }
__device__ __forceinline__ void cpa_wait1()  { asm volatile("cp.async.wait_group 1;" ::); }
__device__ __forceinline__ void cpa_wait0()  { asm volatile("cp.async.wait_group 0;" ::); }

// Tile: 128 rows x 64 halves (128B/row, 8 x 16B chunks). Chunk c of row r is
// stored at r*128 + ((c ^ (r&7))<<4)  -> ldmatrix (8 consecutive rows, same c)
// hits 8 distinct 16B slots per 128B phase: conflict-free.
#define TILE_BYTES 16384
#define NST 3
#define SMEM_BYTES (NST * 2 * TILE_BYTES)   // 96 KB -> 2 CTAs/SM

// cp.async one 128x64-half tile (4 x 16B per thread, 256 threads)
__device__ __forceinline__ void load_tile(uint32_t base, const __half* src,
                                          int ld, int ch, int tid) {
#pragma unroll
    for (int t = 0; t < 4; t++) {
        const int idx = tid + (t << 8);          // 0..1023
        const int r = idx >> 3;                  // 0..127
        const int c = idx & 7;                   // 0..7
        const uint32_t dst = base + (uint32_t)(r * 128 + ((c ^ (r & 7)) << 4));
        cpa16(dst, src + (size_t)r * ld + ch * 64 + c * 8);
    }
}

// ---------------------------------------------------------------------------
// GEMM core: C[128x128] += A[128xK] * B[128xK]^T, half in, fp32 accum.
// 8 warps (4m x 2n), warp tile 32x64, mma m16n8k16. K-chunk 64, 3-stage ring,
// ONE barrier per chunk.
// ---------------------------------------------------------------------------
struct Frag { float acc[2][8][4]; };

__device__ __forceinline__ void gemm_core(Frag& F, char* dsm,
                                          const __half* Asrc, int lda,
                                          const __half* Bsrc, int ldb, int NCH) {
    const int tid = threadIdx.x;
    const int warp = tid >> 5;
    const int wm = (warp & 3) * 32;
    const int wn = (warp >> 2) * 64;
    const int lane = tid & 31;

#pragma unroll
    for (int mi = 0; mi < 2; mi++)
#pragma unroll
        for (int ni = 0; ni < 8; ni++)
#pragma unroll
            for (int j = 0; j < 4; j++) F.acc[mi][ni][j] = 0.f;

    uint32_t sb;
    asm("{ .reg .u64 t; cvta.to.shared.u64 t, %1; cvt.u32.u64 %0, t; }" : "=r"(sb) : "l"(dsm));
    // stage s: A at sb + s*32K, B at +16K
    const uint32_t stBytes = 2 * TILE_BYTES;

    // ldmatrix address precompute
    const int rA = wm + ((lane >> 3) & 1) * 8 + (lane & 7);
    const int cShA = lane >> 4;
    const uint32_t baseA0 = (uint32_t)(rA * 128);
    const uint32_t baseA1 = (uint32_t)((rA + 16) * 128);
    const int swA = rA & 7;
    const int rB = wn + ((lane >> 4) & 1) * 8 + (lane & 7);
    const int cShB = (lane >> 3) & 1;
    const int swB = rB & 7;
    uint32_t baseB[4];
#pragma unroll
    for (int nb = 0; nb < 4; nb++) baseB[nb] = (uint32_t)((rB + 16 * nb) * 128 + TILE_BYTES);

    // prefetch chunks 0, 1
    load_tile(sb, Asrc, lda, 0, tid);
    load_tile(sb + TILE_BYTES, Bsrc, ldb, 0, tid);
    cpa_commit();
    if (NCH > 1) {
        load_tile(sb + stBytes, Asrc, lda, 1, tid);
        load_tile(sb + stBytes + TILE_BYTES, Bsrc, ldb, 1, tid);
        cpa_commit();
    }

    int st = 0;
    for (int ch = 0; ch < NCH; ch++) {
        if (ch + 1 < NCH) cpa_wait1(); else cpa_wait0();
        __syncthreads();   // data for ch visible; all warps done reading stage (ch+2)%NST (last used at ch-1)
        if (ch + 2 < NCH) {
            const uint32_t ns = sb + ((st + 2) % NST) * stBytes;
            load_tile(ns, Asrc, lda, ch + 2, tid);
            load_tile(ns + TILE_BYTES, Bsrc, ldb, ch + 2, tid);
            cpa_commit();
        }

        const uint32_t stage = sb + st * stBytes;
#pragma unroll
        for (int kk = 0; kk < 4; kk++) {
            uint32_t af[2][4], bf[4][4];
            const uint32_t offA = (uint32_t)((((2 * kk + cShA) ^ swA)) << 4);
            ldsm4(af[0], stage + baseA0 + offA);
            ldsm4(af[1], stage + baseA1 + offA);
            const uint32_t offB = (uint32_t)((((2 * kk + cShB) ^ swB)) << 4);
#pragma unroll
            for (int nb = 0; nb < 4; nb++) ldsm4(bf[nb], stage + baseB[nb] + offB);
#pragma unroll
            for (int mi = 0; mi < 2; mi++)
#pragma unroll
                for (int ni = 0; ni < 8; ni++)
                    mma_f16(F.acc[mi][ni], af[mi],
                            bf[ni >> 1][(ni & 1) * 2], bf[ni >> 1][(ni & 1) * 2 + 1]);
        }
        st = (st + 1) % NST;
    }
}

// ---------------------------------------------------------------------------
// Kernel 1: logits = mask(Q @ K^T) * 0.03125  (lower-triangular tiles only)
// ---------------------------------------------------------------------------
__global__ __launch_bounds__(256, 2) void qk_kernel() {
    const int b  = blockIdx.z;
    const int q0 = blockIdx.y << 7;
    const int k0 = blockIdx.x << 7;
    if (k0 > q0) return;

    extern __shared__ __align__(16) char dsm[];
    Frag F;
    gemm_core(F, dsm,
              g_qh + ((size_t)(b * S_LEN + q0)) * D_DIM, D_DIM,
              g_kh + ((size_t)(b * S_LEN + k0)) * D_DIM, D_DIM, D_DIM / 64);

    const int tid = threadIdx.x;
    const int warp = tid >> 5;
    const int wm = (warp & 3) * 32;
    const int wn = (warp >> 2) * 64;
    const int lane = tid & 31;
    const int qr = lane >> 2;
    const int tg = lane & 3;

    float* srow = g_scores + (size_t)b * S_LEN * S_LEN;
#pragma unroll
    for (int mi = 0; mi < 2; mi++) {
#pragma unroll
        for (int half = 0; half < 2; half++) {
            const int qg = q0 + wm + mi * 16 + qr + half * 8;
#pragma unroll
            for (int ni = 0; ni < 8; ni++) {
                const int kg = k0 + wn + ni * 8 + tg * 2;
                float2 v;
                v.x = (kg     > qg) ? -1e9f : F.acc[mi][ni][half * 2 + 0] * 0.03125f;
                v.y = (kg + 1 > qg) ? -1e9f : F.acc[mi][ni][half * 2 + 1] * 0.03125f;
                *reinterpret_cast<float2*>(&srow[(size_t)qg * S_LEN + kg]) = v;
            }
        }
    }
}

// ---------------------------------------------------------------------------
// Kernel 2: row softmax (causal), vectorized float4 / half2x2.
// Thread t covers cols [4t,4t+4) and [4t+1024, 4t+1028).
// ---------------------------------------------------------------------------
__global__ __launch_bounds__(256) void softmax_kernel() {
    const int q = blockIdx.x;
    const int b = blockIdx.y;
    const float4* row = reinterpret_cast<const float4*>(
        g_scores + ((size_t)(b * S_LEN + q)) * S_LEN);
    __half* prow = g_ph + ((size_t)(b * S_LEN + q)) * S_LEN;
    const int tid = threadIdx.x;

    float v[8];
    float mx = -1e30f;
#pragma unroll
    for (int i = 0; i < 2; i++) {
        const int k = 4 * tid + i * 1024;
        float4 f = (k <= q) ? row[tid + i * 256] : make_float4(-1e30f, -1e30f, -1e30f, -1e30f);
        v[4 * i + 0] = (k + 0 <= q) ? f.x : -1e30f;
        v[4 * i + 1] = (k + 1 <= q) ? f.y : -1e30f;
        v[4 * i + 2] = (k + 2 <= q) ? f.z : -1e30f;
        v[4 * i + 3] = (k + 3 <= q) ? f.w : -1e30f;
        mx = fmaxf(mx, fmaxf(fmaxf(v[4 * i], v[4 * i + 1]), fmaxf(v[4 * i + 2], v[4 * i + 3])));
    }
    __shared__ float red[8];
#pragma unroll
    for (int o = 16; o > 0; o >>= 1) mx = fmaxf(mx, __shfl_xor_sync(0xffffffffu, mx, o));
    if ((tid & 31) == 0) red[tid >> 5] = mx;
    __syncthreads();
    float m = red[0];
#pragma unroll
    for (int w = 1; w < 8; w++) m = fmaxf(m, red[w]);
    __syncthreads();

    float s = 0.f;
#pragma unroll
    for (int j = 0; j < 8; j++) {
        const float p = __expf(v[j] - m);   // v=-1e30 -> exp->0
        v[j] = p;
        s += p;
    }
#pragma unroll
    for (int o = 16; o > 0; o >>= 1) s += __shfl_xor_sync(0xffffffffu, s, o);
    if ((tid & 31) == 0) red[tid >> 5] = s;
    __syncthreads();
    float tot = 0.f;
#pragma unroll
    for (int w = 0; w < 8; w++) tot += red[w];

    const float inv = 1.f / tot;
    const int kb = ((q >> 7) + 1) << 7;   // write up to 128 boundary (kb % 4 == 0)
#pragma unroll
    for (int i = 0; i < 2; i++) {
        const int k = 4 * tid + i * 1024;
        if (k < kb) {
            __half2 h[2];
            h[0] = __floats2half2_rn(v[4 * i] * inv, v[4 * i + 1] * inv);
            h[1] = __floats2half2_rn(v[4 * i + 2] * inv, v[4 * i + 3] * inv);
            *reinterpret_cast<uint2*>(prow + k) = *reinterpret_cast<uint2*>(h);
        }
    }
}

// ---------------------------------------------------------------------------
// Kernel 3: O = P @ V  (B = V^T half). Largest-NCH blocks launch FIRST.
// ---------------------------------------------------------------------------
__global__ __launch_bounds__(256, 2) void pv_kernel(float* __restrict__ O) {
    const int b  = blockIdx.z;
    const int q0 = (15 - blockIdx.y) << 7;   // LPT: big CTAs first
    const int d0 = blockIdx.x << 7;

    extern __shared__ __align__(16) char dsm[];
    Frag F;
    const int NCH = (q0 + 128) >> 6;
    gemm_core(F, dsm,
              g_ph + ((size_t)(b * S_LEN + q0)) * S_LEN, S_LEN,
              g_vth + ((size_t)(b * D_DIM + d0)) * S_LEN, S_LEN, NCH);

    const int tid = threadIdx.x;
    const int warp = tid >> 5;
    const int wm = (warp & 3) * 32;
    const int wn = (warp >> 2) * 64;
    const int lane = tid & 31;
    const int qr = lane >> 2;
    const int tg = lane & 3;

#pragma unroll
    for (int mi = 0; mi < 2; mi++) {
#pragma unroll
        for (int half = 0; half < 2; half++) {
            const int qg = q0 + wm + mi * 16 + qr + half * 8;
            float* orow = O + ((size_t)(b * S_LEN + qg)) * D_DIM + d0;
#pragma unroll
            for (int ni = 0; ni < 8; ni++) {
                const int cg = wn + ni * 8 + tg * 2;
                float2 v;
                v.x = F.acc[mi][ni][half * 2 + 0];
                v.y = F.acc[mi][ni][half * 2 + 1];
                *reinterpret_cast<float2*>(&orow[cg]) = v;
            }
        }
    }
}

// ---------------------------------------------------------------------------
// Pre-pass: Q,K -> half (plain row-major)
// ---------------------------------------------------------------------------
__global__ __launch_bounds__(256) void conv_qk(const float4* __restrict__ Q,
                                               const float4* __restrict__ K) {
    const size_t i = (size_t)blockIdx.x * blockDim.x + threadIdx.x;  // 8 floats each
    const float4* src = blockIdx.y == 0 ? Q : K;
    __half* dst = blockIdx.y == 0 ? g_qh : g_kh;
    const float4 a = src[2 * i];
    const float4 b = src[2 * i + 1];
    __half2 h[4];
    h[0] = __floats2half2_rn(a.x, a.y);
    h[1] = __floats2half2_rn(a.z, a.w);
    h[2] = __floats2half2_rn(b.x, b.y);
    h[3] = __floats2half2_rn(b.z, b.w);
    *reinterpret_cast<uint4*>(dst + i * 8) = *reinterpret_cast<uint4*>(h);
}

// ---------------------------------------------------------------------------
// Pre-pass: V^T -> half.  g_vth[b][d][k] = (half)V[b][k][d]
// ---------------------------------------------------------------------------
__global__ __launch_bounds__(256) void transpose_v_kernel(const float* __restrict__ V) {
    __shared__ float tile[32][33];
    const int b  = blockIdx.z;
    const int k0 = blockIdx.x << 5;
    const int d0 = blockIdx.y << 5;
    const int tx = threadIdx.x & 31, ty = threadIdx.x >> 5;
    const float* Vb = V + (size_t)b * S_LEN * D_DIM;
#pragma unroll
    for (int i = 0; i < 4; i++)
        tile[ty + 8 * i][tx] = Vb[(size_t)(k0 + ty + 8 * i) * D_DIM + d0 + tx];
    __syncthreads();
    __half* Tb = g_vth + (size_t)b * D_DIM * S_LEN;
#pragma unroll
    for (int i = 0; i < 4; i++)
        Tb[(size_t)(d0 + ty + 8 * i) * S_LEN + k0 + tx] = __float2half(tile[tx][ty + 8 * i]);
}

// ---------------------------------------------------------------------------
extern "C" void kernel_launch(void* const* d_in, const int* in_sizes, int n_in,
                              void* d_out, int out_size) {
    const float* Q = (const float*)d_in[0];
    const float* K = (const float*)d_in[1];
    const float* V = (const float*)d_in[2];
    float* O = (float*)d_out;

    static bool attr_done = false;
    if (!attr_done) {
        cudaFuncSetAttribute(qk_kernel, cudaFuncAttributeMaxDynamicSharedMemorySize, SMEM_BYTES);
        cudaFuncSetAttribute(pv_kernel, cudaFuncAttributeMaxDynamicSharedMemorySize, SMEM_BYTES);
        attr_done = true;
    }

    conv_qk<<<dim3(8192, 2), 256>>>((const float4*)Q, (const float4*)K);
    transpose_v_kernel<<<dim3(64, 32, 8), 256>>>(V);
    qk_kernel<<<dim3(16, 16, 8), 256, SMEM_BYTES>>>();
    softmax_kernel<<<dim3(2048, 8), 256>>>();
    pv_kernel<<<dim3(8, 16, 8), 256, SMEM_BYTES>>>(O);
}

// round 6
// speedup vs baseline: 2.5082x; 1.0163x over previous
#include <cuda_runtime.h>
#include <cuda_fp16.h>
#include <cstdint>

#define S_LEN 2048
#define D_DIM 1024
#define B_SZ  8

// Scratch (static __device__ per allocation rules)
static __device__ __half g_ph[(size_t)B_SZ * S_LEN * S_LEN];      // logits -> P (half, in-place)
static __device__ __half g_qh[(size_t)B_SZ * S_LEN * D_DIM];      // Q half
static __device__ __half g_kh[(size_t)B_SZ * S_LEN * D_DIM];      // K half
static __device__ __half g_vth[(size_t)B_SZ * D_DIM * S_LEN];     // V^T half

// ---------------------------------------------------------------------------
// helpers
// ---------------------------------------------------------------------------
__device__ __forceinline__ void mma_f16(float* d, const uint32_t* a, uint32_t b0, uint32_t b1) {
    asm volatile(
        "mma.sync.aligned.m16n8k16.row.col.f32.f16.f16.f32 "
        "{%0,%1,%2,%3}, {%4,%5,%6,%7}, {%8,%9}, {%0,%1,%2,%3};\n"
        : "+f"(d[0]), "+f"(d[1]), "+f"(d[2]), "+f"(d[3])
        : "r"(a[0]), "r"(a[1]), "r"(a[2]), "r"(a[3]), "r"(b0), "r"(b1));
}
__device__ __forceinline__ void ldsm4(uint32_t* r, uint32_t addr) {
    asm volatile("ldmatrix.sync.aligned.m8n8.x4.shared.b16 {%0,%1,%2,%3}, [%4];"
                 : "=r"(r[0]), "=r"(r[1]), "=r"(r[2]), "=r"(r[3]) : "r"(addr));
}
__device__ __forceinline__ void cpa16(uint32_t s, const void* g) {
    asm volatile("cp.async.cg.shared.global [%0], [%1], 16;" :: "r"(s), "l"(g));
}
__device__ __forceinline__ void cpa_commit() { asm volatile("cp.async.commit_group;" ::); }
__device__ __forceinline__ void cpa_wait1()  { asm volatile("cp.async.wait_group 1;" ::); }
__device__ __forceinline__ void cpa_wait0()  { asm volatile("cp.async.wait_group 0;" ::); }

// Tile: 128 rows x 64 halves (128B/row, 8 x 16B chunks). Chunk c of row r is
// stored at r*128 + ((c ^ (r&7))<<4)  -> ldmatrix (8 consecutive rows, same c)
// hits 8 distinct 16B slots per 128B phase: conflict-free.
#define TILE_BYTES 16384
#define NST 3
#define SMEM_BYTES (NST * 2 * TILE_BYTES)   // 96 KB -> 2 CTAs/SM

// cp.async one 128x64-half tile (4 x 16B per thread, 256 threads)
__device__ __forceinline__ void load_tile(uint32_t base, const __half* src,
                                          int ld, int ch, int tid) {
#pragma unroll
    for (int t = 0; t < 4; t++) {
        const int idx = tid + (t << 8);          // 0..1023
        const int r = idx >> 3;                  // 0..127
        const int c = idx & 7;                   // 0..7
        const uint32_t dst = base + (uint32_t)(r * 128 + ((c ^ (r & 7)) << 4));
        cpa16(dst, src + (size_t)r * ld + ch * 64 + c * 8);
    }
}

// ---------------------------------------------------------------------------
// GEMM core: C[128x128] += A[128xK] * B[128xK]^T, half in, fp32 accum.
// 8 warps (4m x 2n), warp tile 32x64, mma m16n8k16. K-chunk 64, 3-stage ring,
// ONE barrier per chunk.
// ---------------------------------------------------------------------------
struct Frag { float acc[2][8][4]; };

__device__ __forceinline__ void gemm_core(Frag& F, char* dsm,
                                          const __half* Asrc, int lda,
                                          const __half* Bsrc, int ldb, int NCH) {
    const int tid = threadIdx.x;
    const int warp = tid >> 5;
    const int wm = (warp & 3) * 32;
    const int wn = (warp >> 2) * 64;
    const int lane = tid & 31;

#pragma unroll
    for (int mi = 0; mi < 2; mi++)
#pragma unroll
        for (int ni = 0; ni < 8; ni++)
#pragma unroll
            for (int j = 0; j < 4; j++) F.acc[mi][ni][j] = 0.f;

    uint32_t sb;
    asm("{ .reg .u64 t; cvta.to.shared.u64 t, %1; cvt.u32.u64 %0, t; }" : "=r"(sb) : "l"(dsm));
    const uint32_t stBytes = 2 * TILE_BYTES;

    const int rA = wm + ((lane >> 3) & 1) * 8 + (lane & 7);
    const int cShA = lane >> 4;
    const uint32_t baseA0 = (uint32_t)(rA * 128);
    const uint32_t baseA1 = (uint32_t)((rA + 16) * 128);
    const int swA = rA & 7;
    const int rB = wn + ((lane >> 4) & 1) * 8 + (lane & 7);
    const int cShB = (lane >> 3) & 1;
    const int swB = rB & 7;
    uint32_t baseB[4];
#pragma unroll
    for (int nb = 0; nb < 4; nb++) baseB[nb] = (uint32_t)((rB + 16 * nb) * 128 + TILE_BYTES);

    load_tile(sb, Asrc, lda, 0, tid);
    load_tile(sb + TILE_BYTES, Bsrc, ldb, 0, tid);
    cpa_commit();
    if (NCH > 1) {
        load_tile(sb + stBytes, Asrc, lda, 1, tid);
        load_tile(sb + stBytes + TILE_BYTES, Bsrc, ldb, 1, tid);
        cpa_commit();
    }

    int st = 0;
    for (int ch = 0; ch < NCH; ch++) {
        if (ch + 1 < NCH) cpa_wait1(); else cpa_wait0();
        __syncthreads();   // data for ch visible; stage (ch+2)%NST free (last read at ch-1)
        if (ch + 2 < NCH) {
            const uint32_t ns = sb + ((st + 2) % NST) * stBytes;
            load_tile(ns, Asrc, lda, ch + 2, tid);
            load_tile(ns + TILE_BYTES, Bsrc, ldb, ch + 2, tid);
            cpa_commit();
        }

        const uint32_t stage = sb + st * stBytes;
#pragma unroll
        for (int kk = 0; kk < 4; kk++) {
            uint32_t af[2][4], bf[4][4];
            const uint32_t offA = (uint32_t)((((2 * kk + cShA) ^ swA)) << 4);
            ldsm4(af[0], stage + baseA0 + offA);
            ldsm4(af[1], stage + baseA1 + offA);
            const uint32_t offB = (uint32_t)((((2 * kk + cShB) ^ swB)) << 4);
#pragma unroll
            for (int nb = 0; nb < 4; nb++) ldsm4(bf[nb], stage + baseB[nb] + offB);
#pragma unroll
            for (int mi = 0; mi < 2; mi++)
#pragma unroll
                for (int ni = 0; ni < 8; ni++)
                    mma_f16(F.acc[mi][ni], af[mi],
                            bf[ni >> 1][(ni & 1) * 2], bf[ni >> 1][(ni & 1) * 2 + 1]);
        }
        st = (st + 1) % NST;
    }
}

// ---------------------------------------------------------------------------
// Kernel 1: logits = (Q @ K^T) * 0.03125 stored as HALF, lower-tri tiles only.
// No mask here: softmax's k<=q predicate ignores above-diagonal entries.
// ---------------------------------------------------------------------------
__global__ __launch_bounds__(256, 2) void qk_kernel() {
    const int b  = blockIdx.z;
    const int q0 = blockIdx.y << 7;
    const int k0 = blockIdx.x << 7;
    if (k0 > q0) return;

    extern __shared__ __align__(16) char dsm[];
    Frag F;
    gemm_core(F, dsm,
              g_qh + ((size_t)(b * S_LEN + q0)) * D_DIM, D_DIM,
              g_kh + ((size_t)(b * S_LEN + k0)) * D_DIM, D_DIM, D_DIM / 64);

    const int tid = threadIdx.x;
    const int warp = tid >> 5;
    const int wm = (warp & 3) * 32;
    const int wn = (warp >> 2) * 64;
    const int lane = tid & 31;
    const int qr = lane >> 2;
    const int tg = lane & 3;

    __half* srow = g_ph + (size_t)b * S_LEN * S_LEN;
#pragma unroll
    for (int mi = 0; mi < 2; mi++) {
#pragma unroll
        for (int half = 0; half < 2; half++) {
            const int qg = q0 + wm + mi * 16 + qr + half * 8;
#pragma unroll
            for (int ni = 0; ni < 8; ni++) {
                const int kg = k0 + wn + ni * 8 + tg * 2;
                const __half2 h = __floats2half2_rn(F.acc[mi][ni][half * 2 + 0] * 0.03125f,
                                                    F.acc[mi][ni][half * 2 + 1] * 0.03125f);
                *reinterpret_cast<__half2*>(&srow[(size_t)qg * S_LEN + kg]) = h;
            }
        }
    }
}

// ---------------------------------------------------------------------------
// Kernel 2: row softmax (causal), half in-place. One uint4 (8 halves) per thread.
// Zero-fills masked entries up to the 128 tile boundary.
// ---------------------------------------------------------------------------
__global__ __launch_bounds__(256) void softmax_kernel() {
    const int q = blockIdx.x;
    const int b = blockIdx.y;
    __half* prow = g_ph + ((size_t)(b * S_LEN + q)) * S_LEN;
    const int tid = threadIdx.x;
    const int k0 = tid * 8;

    uint4 raw = *reinterpret_cast<const uint4*>(prow + k0);
    const __half2* h2 = reinterpret_cast<const __half2*>(&raw);
    float v[8];
#pragma unroll
    for (int j = 0; j < 4; j++) {
        const float2 f = __half22float2(h2[j]);
        v[2 * j + 0] = (k0 + 2 * j + 0 <= q) ? f.x : -1e30f;
        v[2 * j + 1] = (k0 + 2 * j + 1 <= q) ? f.y : -1e30f;
    }

    float mx = v[0];
#pragma unroll
    for (int j = 1; j < 8; j++) mx = fmaxf(mx, v[j]);
    __shared__ float red[8];
#pragma unroll
    for (int o = 16; o > 0; o >>= 1) mx = fmaxf(mx, __shfl_xor_sync(0xffffffffu, mx, o));
    if ((tid & 31) == 0) red[tid >> 5] = mx;
    __syncthreads();
    float m = red[0];
#pragma unroll
    for (int w = 1; w < 8; w++) m = fmaxf(m, red[w]);
    __syncthreads();

    float s = 0.f;
#pragma unroll
    for (int j = 0; j < 8; j++) {
        const float p = __expf(v[j] - m);   // -1e30 -> 0
        v[j] = p;
        s += p;
    }
#pragma unroll
    for (int o = 16; o > 0; o >>= 1) s += __shfl_xor_sync(0xffffffffu, s, o);
    if ((tid & 31) == 0) red[tid >> 5] = s;
    __syncthreads();
    float tot = 0.f;
#pragma unroll
    for (int w = 0; w < 8; w++) tot += red[w];

    const float inv = 1.f / tot;
    const int kb = ((q >> 7) + 1) << 7;   // kb % 8 == 0
    if (k0 < kb) {
        uint4 out;
        __half2* o2 = reinterpret_cast<__half2*>(&out);
#pragma unroll
        for (int j = 0; j < 4; j++)
            o2[j] = __floats2half2_rn(v[2 * j] * inv, v[2 * j + 1] * inv);
        *reinterpret_cast<uint4*>(prow + k0) = out;
    }
}

// ---------------------------------------------------------------------------
// Kernel 3: O = P @ V  (B = V^T half). Largest-NCH blocks launch FIRST.
// ---------------------------------------------------------------------------
__global__ __launch_bounds__(256, 2) void pv_kernel(float* __restrict__ O) {
    const int b  = blockIdx.z;
    const int q0 = (15 - blockIdx.y) << 7;   // LPT: big CTAs first
    const int d0 = blockIdx.x << 7;

    extern __shared__ __align__(16) char dsm[];
    Frag F;
    const int NCH = (q0 + 128) >> 6;
    gemm_core(F, dsm,
              g_ph + ((size_t)(b * S_LEN + q0)) * S_LEN, S_LEN,
              g_vth + ((size_t)(b * D_DIM + d0)) * S_LEN, S_LEN, NCH);

    const int tid = threadIdx.x;
    const int warp = tid >> 5;
    const int wm = (warp & 3) * 32;
    const int wn = (warp >> 2) * 64;
    const int lane = tid & 31;
    const int qr = lane >> 2;
    const int tg = lane & 3;

#pragma unroll
    for (int mi = 0; mi < 2; mi++) {
#pragma unroll
        for (int half = 0; half < 2; half++) {
            const int qg = q0 + wm + mi * 16 + qr + half * 8;
            float* orow = O + ((size_t)(b * S_LEN + qg)) * D_DIM + d0;
#pragma unroll
            for (int ni = 0; ni < 8; ni++) {
                const int cg = wn + ni * 8 + tg * 2;
                float2 v;
                v.x = F.acc[mi][ni][half * 2 + 0];
                v.y = F.acc[mi][ni][half * 2 + 1];
                *reinterpret_cast<float2*>(&orow[cg]) = v;
            }
        }
    }
}

// ---------------------------------------------------------------------------
// Pre-pass: Q,K -> half (plain row-major)
// ---------------------------------------------------------------------------
__global__ __launch_bounds__(256) void conv_qk(const float4* __restrict__ Q,
                                               const float4* __restrict__ K) {
    const size_t i = (size_t)blockIdx.x * blockDim.x + threadIdx.x;  // 8 floats each
    const float4* src = blockIdx.y == 0 ? Q : K;
    __half* dst = blockIdx.y == 0 ? g_qh : g_kh;
    const float4 a = src[2 * i];
    const float4 b = src[2 * i + 1];
    __half2 h[4];
    h[0] = __floats2half2_rn(a.x, a.y);
    h[1] = __floats2half2_rn(a.z, a.w);
    h[2] = __floats2half2_rn(b.x, b.y);
    h[3] = __floats2half2_rn(b.z, b.w);
    *reinterpret_cast<uint4*>(dst + i * 8) = *reinterpret_cast<uint4*>(h);
}

// ---------------------------------------------------------------------------
// Pre-pass: V^T -> half.  g_vth[b][d][k] = (half)V[b][k][d]
// ---------------------------------------------------------------------------
__global__ __launch_bounds__(256) void transpose_v_kernel(const float* __restrict__ V) {
    __shared__ float tile[32][33];
    const int b  = blockIdx.z;
    const int k0 = blockIdx.x << 5;
    const int d0 = blockIdx.y << 5;
    const int tx = threadIdx.x & 31, ty = threadIdx.x >> 5;
    const float* Vb = V + (size_t)b * S_LEN * D_DIM;
#pragma unroll
    for (int i = 0; i < 4; i++)
        tile[ty + 8 * i][tx] = Vb[(size_t)(k0 + ty + 8 * i) * D_DIM + d0 + tx];
    __syncthreads();
    __half* Tb = g_vth + (size_t)b * D_DIM * S_LEN;
#pragma unroll
    for (int i = 0; i < 4; i++)
        Tb[(size_t)(d0 + ty + 8 * i) * S_LEN + k0 + tx] = __float2half(tile[tx][ty + 8 * i]);
}

// ---------------------------------------------------------------------------
extern "C" void kernel_launch(void* const* d_in, const int* in_sizes, int n_in,
                              void* d_out, int out_size) {
    const float* Q = (const float*)d_in[0];
    const float* K = (const float*)d_in[1];
    const float* V = (const float*)d_in[2];
    float* O = (float*)d_out;

    static cudaStream_t s2 = nullptr;
    static cudaEvent_t ev1 = nullptr, ev2 = nullptr;
    if (!s2) {   // first call is the (uncaptured) correctness run
        cudaStreamCreateWithFlags(&s2, cudaStreamNonBlocking);
        cudaEventCreateWithFlags(&ev1, cudaEventDisableTiming);
        cudaEventCreateWithFlags(&ev2, cudaEventDisableTiming);
        cudaFuncSetAttribute(qk_kernel, cudaFuncAttributeMaxDynamicSharedMemorySize, SMEM_BYTES);
        cudaFuncSetAttribute(pv_kernel, cudaFuncAttributeMaxDynamicSharedMemorySize, SMEM_BYTES);
    }

    // fork: V^T runs on s2, overlapping conv_qk + qk + softmax on the main stream
    cudaEventRecord(ev1, 0);
    cudaStreamWaitEvent(s2, ev1, 0);
    transpose_v_kernel<<<dim3(64, 32, 8), 256, 0, s2>>>(V);
    cudaEventRecord(ev2, s2);

    conv_qk<<<dim3(8192, 2), 256>>>((const float4*)Q, (const float4*)K);
    qk_kernel<<<dim3(16, 16, 8), 256, SMEM_BYTES>>>();
    softmax_kernel<<<dim3(2048, 8), 256>>>();

    // join: pv needs V^T
    cudaStreamWaitEvent(0, ev2, 0);
    pv_kernel<<<dim3(8, 16, 8), 256, SMEM_BYTES>>>(O);
}